// round 8
// baseline (speedup 1.0000x reference)
#include <cuda_runtime.h>
#include <cuda_bf16.h>
#include <math.h>
#include <stdint.h>

#define BB 32
#define SS 8192
#define DD 256
#define HH 256

// device-global scratch (allocation-free rule)
__device__ float g_inp[BB * HH];
__device__ __nv_bfloat16 g_Bh[HH * DD];      // W_ctx hi (bf16), [h][d]
__device__ __nv_bfloat16 g_Bl[HH * DD];      // W_ctx lo
__device__ float g_att[BB * SS];

// ---------------------------------------------------------------------------
__device__ __forceinline__ uint32_t smem_u32(const void* p) {
    uint32_t a;
    asm("{ .reg .u64 t; cvta.to.shared.u64 t, %1; cvt.u32.u64 %0, t; }" : "=r"(a) : "l"(p));
    return a;
}
#define CP_ASYNC16(dst, src) \
    asm volatile("cp.async.cg.shared.global [%0], [%1], 16;" :: "r"(dst), "l"(src))
#define CP_COMMIT() asm volatile("cp.async.commit_group;" ::: "memory")
#define CP_WAIT2()  asm volatile("cp.async.wait_group 2;" ::: "memory")

#define LDSM4(r0, r1, r2, r3, a) \
    asm volatile("ldmatrix.sync.aligned.m8n8.x4.shared.b16 {%0,%1,%2,%3}, [%4];" \
        : "=r"(r0), "=r"(r1), "=r"(r2), "=r"(r3) : "r"(a))

#define MMA_BF16(c, A, b0, b1) \
    asm volatile("mma.sync.aligned.m16n8k16.row.col.f32.bf16.bf16.f32 " \
        "{%0,%1,%2,%3},{%4,%5,%6,%7},{%8,%9},{%0,%1,%2,%3};" \
        : "+f"((c)[0]), "+f"((c)[1]), "+f"((c)[2]), "+f"((c)[3]) \
        : "r"((A)[0]), "r"((A)[1]), "r"((A)[2]), "r"((A)[3]), "r"(b0), "r"(b1))

// ---------------------------------------------------------------------------
// Kernel 1: inp[b,h] = b_in[h] + sum_d x[b,d] * W_in[h,d]
// ---------------------------------------------------------------------------
__global__ void k_inp(const float* __restrict__ x, const float* __restrict__ W_in,
                      const float* __restrict__ b_in) {
    int b = blockIdx.x, h = threadIdx.x;
    __shared__ float xs[HH];
    xs[h] = x[b * HH + h];
    __syncthreads();
    float acc = b_in[h];
    const float* w = W_in + h * HH;
#pragma unroll 8
    for (int d0 = 0; d0 < HH; d0 += 4) {
        float4 w4 = *(const float4*)(w + d0);
        acc += xs[d0] * w4.x + xs[d0+1] * w4.y + xs[d0+2] * w4.z + xs[d0+3] * w4.w;
    }
    g_inp[b * HH + h] = acc;
}

// ---------------------------------------------------------------------------
// Kernel 2: split W_ctx fp32 -> bf16 hi/lo
// ---------------------------------------------------------------------------
__global__ void k_wsplit(const float* __restrict__ W) {
    int i = blockIdx.x * 256 + threadIdx.x;
    float v = W[i];
    __nv_bfloat16 h = __float2bfloat16_rn(v);
    g_Bh[i] = h;
    g_Bl[i] = __float2bfloat16_rn(v - __bfloat162float(h));
}

// ---------------------------------------------------------------------------
// Kernel 3: split-bf16 HMMA GEMM, 3-stage cp.async pipeline, KT=16.
// CTA: M=64 rows, N=256, K=256 in 16 tiles of 16.
// 8 warps: wm = wid&1 (32 rows), wn = wid>>1 (64 cols).
// acc = Ah*Bh + Ah*Bl + Al*Bh   (lo*lo dropped, ~2^-18)
// ---------------------------------------------------------------------------
#define MT 64
#define KT 16
#define NT (DD / KT)       // 16 k-tiles
#define PITCH 48           // 16 bf16 = 32B data + 16B pad (16B-aligned rows)
// smem byte offsets (3 stages each)
#define OFF_AH  0          // + s*3072   (64 rows * 48B)
#define OFF_AL  9216       // + s*3072
#define OFF_BH  18432      // + s*12288  (256 rows * 48B)
#define OFF_BL  55296      // + s*12288
#define OFF_IB  92160
#define OFF_V   93184
#define OFF_P   94208
#define SMEM_TOTAL 95232

__global__ __launch_bounds__(256, 2) void k_main(const float* __restrict__ context,
                                                 const float* __restrict__ b_ctx,
                                                 const float* __restrict__ V) {
    extern __shared__ char smem[];
    uint32_t sb = smem_u32(smem);
    int tid = threadIdx.x;
    int wid = tid >> 5, lid = tid & 31;
    int wm = wid & 1, wn = wid >> 1;
    int b = blockIdx.y;
    int m0 = blockIdx.x * MT;

    float* ibs = (float*)(smem + OFF_IB);
    float* vvs = (float*)(smem + OFF_V);
    ibs[tid] = g_inp[b * HH + tid] + b_ctx[tid];
    vvs[tid] = V[tid];

    const float* ctx = context + ((long)b * SS + m0) * DD;
    int arow = tid >> 2, aseg = tid & 3;     // A: 1 float4/thread/ktile

    // ---- helpers as macros over (stage st) ----
#define LDG_A(dst4, st) { dst4 = *(const float4*)(ctx + arow * DD + (st) * KT + aseg * 4); }
#define STS_A(v4, st) { \
        __nv_bfloat16 h0 = __float2bfloat16_rn(v4.x), h1 = __float2bfloat16_rn(v4.y); \
        __nv_bfloat16 h2 = __float2bfloat16_rn(v4.z), h3 = __float2bfloat16_rn(v4.w); \
        __nv_bfloat16 l0 = __float2bfloat16_rn(v4.x - __bfloat162float(h0)); \
        __nv_bfloat16 l1 = __float2bfloat16_rn(v4.y - __bfloat162float(h1)); \
        __nv_bfloat16 l2 = __float2bfloat16_rn(v4.z - __bfloat162float(h2)); \
        __nv_bfloat16 l3 = __float2bfloat16_rn(v4.w - __bfloat162float(h3)); \
        uint2 ph = make_uint2((uint32_t)__bfloat16_as_ushort(h0) | ((uint32_t)__bfloat16_as_ushort(h1) << 16), \
                              (uint32_t)__bfloat16_as_ushort(h2) | ((uint32_t)__bfloat16_as_ushort(h3) << 16)); \
        uint2 pl = make_uint2((uint32_t)__bfloat16_as_ushort(l0) | ((uint32_t)__bfloat16_as_ushort(l1) << 16), \
                              (uint32_t)__bfloat16_as_ushort(l2) | ((uint32_t)__bfloat16_as_ushort(l3) << 16)); \
        char* base = smem + ((st) % 3) * 3072 + arow * PITCH + aseg * 8; \
        *(uint2*)(base + OFF_AH) = ph; \
        *(uint2*)(base + OFF_AL) = pl; \
    }
#define ISSUE_B(st) { \
        int k0 = (st) * KT; \
        _Pragma("unroll") \
        for (int r = 0; r < 4; r++) { \
            int ch = tid + 256 * r; \
            int mat = ch >> 9, row = (ch >> 1) & 255, half = ch & 1; \
            const __nv_bfloat16* src = (mat ? g_Bl : g_Bh) + row * DD + k0 + half * 8; \
            uint32_t dst = sb + OFF_BH + mat * (OFF_BL - OFF_BH) + ((st) % 3) * 12288 + row * PITCH + half * 16; \
            CP_ASYNC16(dst, src); \
        } \
    }

    // ---- prologue: stages 0,1 fully issued; A for stage 2 in regs ----
    {
        float4 f0, f1;
        LDG_A(f0, 0); LDG_A(f1, 1);
        STS_A(f0, 0); STS_A(f1, 1);
        ISSUE_B(0); CP_COMMIT();
        ISSUE_B(1); CP_COMMIT();
    }
    float4 a4;
    LDG_A(a4, 2);

    float c[2][8][4];
#pragma unroll
    for (int mi = 0; mi < 2; mi++)
#pragma unroll
        for (int j = 0; j < 8; j++)
#pragma unroll
            for (int e = 0; e < 4; e++) c[mi][j][e] = 0.f;

#pragma unroll 1
    for (int kt = 0; kt < NT; kt++) {
        int s = kt % 3;
        __syncthreads();                       // all warps done with slot being refilled
        if (kt + 2 < NT) {
            STS_A(a4, kt + 2);
            if (kt + 3 < NT) LDG_A(a4, kt + 3);
            ISSUE_B(kt + 2);
        }
        CP_COMMIT();                           // always commit (empty ok) for wait bookkeeping
        CP_WAIT2();                            // stage kt complete
        __syncthreads();                       // stage kt visible to all warps

        // ---- MMAs over stage kt ----
        uint32_t aoff = sb + s * 3072 + (lid >> 4) * 16;
        uint32_t boff = sb + OFF_BH + s * 12288 + ((lid >> 3) & 1) * 16;
        uint32_t aH[2][4], aL[2][4], bH[4][4], bL[4][4];
        int arow_f = wm * 32 + (lid & 15);
#pragma unroll
        for (int mi = 0; mi < 2; mi++) {
            uint32_t ad = aoff + (arow_f + mi * 16) * PITCH;
            LDSM4(aH[mi][0], aH[mi][1], aH[mi][2], aH[mi][3], ad + OFF_AH);
            LDSM4(aL[mi][0], aL[mi][1], aL[mi][2], aL[mi][3], ad + OFF_AL);
        }
        int brow_f = wn * 64 + (lid & 7) + ((lid >> 4) * 8);
#pragma unroll
        for (int jp = 0; jp < 4; jp++) {
            uint32_t bd = boff + (brow_f + jp * 16) * PITCH;
            LDSM4(bH[jp][0], bH[jp][1], bH[jp][2], bH[jp][3], bd);
            LDSM4(bL[jp][0], bL[jp][1], bL[jp][2], bL[jp][3], bd + (OFF_BL - OFF_BH));
        }
#pragma unroll
        for (int mi = 0; mi < 2; mi++)
#pragma unroll
            for (int j = 0; j < 8; j++) {
                uint32_t h0 = bH[j >> 1][(j & 1) * 2], h1 = bH[j >> 1][(j & 1) * 2 + 1];
                uint32_t l0 = bL[j >> 1][(j & 1) * 2], l1 = bL[j >> 1][(j & 1) * 2 + 1];
                MMA_BF16(c[mi][j], aH[mi], h0, h1);
                MMA_BF16(c[mi][j], aH[mi], l0, l1);
                MMA_BF16(c[mi][j], aL[mi], h0, h1);
            }
    }

    // ---- epilogue: per-row tanh-dot with V ----
    {
        int q = lid & 3, g = lid >> 2;
        float ps[2][2] = {{0.f, 0.f}, {0.f, 0.f}};
#pragma unroll
        for (int mi = 0; mi < 2; mi++)
#pragma unroll
            for (int j = 0; j < 8; j++) {
                int h0 = wn * 64 + j * 8 + q * 2;
                ps[mi][0] += vvs[h0]   * tanhf(c[mi][j][0] + ibs[h0]);
                ps[mi][0] += vvs[h0+1] * tanhf(c[mi][j][1] + ibs[h0+1]);
                ps[mi][1] += vvs[h0]   * tanhf(c[mi][j][2] + ibs[h0]);
                ps[mi][1] += vvs[h0+1] * tanhf(c[mi][j][3] + ibs[h0+1]);
            }
#pragma unroll
        for (int off = 1; off <= 2; off <<= 1) {
#pragma unroll
            for (int mi = 0; mi < 2; mi++) {
                ps[mi][0] += __shfl_xor_sync(0xffffffffu, ps[mi][0], off);
                ps[mi][1] += __shfl_xor_sync(0xffffffffu, ps[mi][1], off);
            }
        }
        float* part = (float*)(smem + OFF_P);
        __syncthreads();
        if (q == 0) {
#pragma unroll
            for (int mi = 0; mi < 2; mi++) {
                part[(wm * 32 + mi * 16 + g) * 4 + wn]     = ps[mi][0];
                part[(wm * 32 + mi * 16 + g + 8) * 4 + wn] = ps[mi][1];
            }
        }
        __syncthreads();
        if (tid < MT) {
            float ssum = part[tid * 4] + part[tid * 4 + 1] + part[tid * 4 + 2] + part[tid * 4 + 3];
            g_att[b * SS + m0 + tid] = 10.f * tanhf(ssum);
        }
    }
}

// ---------------------------------------------------------------------------
// Kernel 4: mask echo + single-pass masked argmax + p = exp(max)/sum(exp).
// ---------------------------------------------------------------------------
__global__ __launch_bounds__(1024) void k_reduce(const int* __restrict__ mask,
                                                 float* __restrict__ out) {
    int b = blockIdx.x, tid = threadIdx.x;
    __shared__ float smax[1024], ssum[1024];
    __shared__ int   sidx[1024];

    float best = -INFINITY, se = 0.f;
    int bidx = 0x7fffffff;
    for (int s = tid; s < SS; s += 1024) {
        int m = mask[b * SS + s];
        out[2 * BB + b * SS + s] = m ? 1.f : 0.f;
        if (m) {
            float v = g_att[b * SS + s];
            se += expf(v);
            if (v > best || (v == best && s < bidx)) { best = v; bidx = s; }
        }
    }
    smax[tid] = best; sidx[tid] = bidx; ssum[tid] = se;
    __syncthreads();
    for (int off = 512; off; off >>= 1) {
        if (tid < off) {
            float v = smax[tid + off]; int ix = sidx[tid + off];
            if (v > smax[tid] || (v == smax[tid] && ix < sidx[tid])) {
                smax[tid] = v; sidx[tid] = ix;
            }
            ssum[tid] += ssum[tid + off];
        }
        __syncthreads();
    }
    if (tid == 0) {
        float rowmax = smax[0];
        out[b]      = (float)((rowmax == -INFINITY) ? 0 : sidx[0]);
        out[BB + b] = expf(rowmax) / ssum[0];
    }
}

// ---------------------------------------------------------------------------
extern "C" void kernel_launch(void* const* d_in, const int* in_sizes, int n_in,
                              void* d_out, int out_size) {
    const float* x      = (const float*)d_in[0];
    const float* contex = (const float*)d_in[1];
    const int*   mask   = (const int*)  d_in[2];
    const float* W_in   = (const float*)d_in[3];
    const float* b_in   = (const float*)d_in[4];
    const float* W_ctx  = (const float*)d_in[5];
    const float* b_ctx  = (const float*)d_in[6];
    const float* V      = (const float*)d_in[7];
    float* out = (float*)d_out;

    cudaFuncSetAttribute(k_main, cudaFuncAttributeMaxDynamicSharedMemorySize, SMEM_TOTAL);

    k_inp<<<BB, HH>>>(x, W_in, b_in);
    k_wsplit<<<HH * DD / 256, 256>>>(W_ctx);
    k_main<<<dim3(SS / MT, BB), 256, SMEM_TOTAL>>>(contex, b_ctx, V);
    k_reduce<<<BB, 1024>>>(mask, out);
}

// round 10
// speedup vs baseline: 1.0599x; 1.0599x over previous
#include <cuda_runtime.h>
#include <cuda_bf16.h>
#include <math.h>
#include <stdint.h>

#define BB 32
#define SS 8192
#define DD 256
#define HH 256

// device-global scratch (allocation-free rule)
__device__ float g_inp[BB * HH];
__device__ __nv_bfloat16 g_Bh[HH * DD];      // W_ctx hi (bf16), [h][d]
__device__ __nv_bfloat16 g_Bl[HH * DD];      // W_ctx lo
__device__ float g_att[BB * SS];

// ---------------------------------------------------------------------------
__device__ __forceinline__ uint32_t smem_u32(const void* p) {
    uint32_t a;
    asm("{ .reg .u64 t; cvta.to.shared.u64 t, %1; cvt.u32.u64 %0, t; }" : "=r"(a) : "l"(p));
    return a;
}
#define CP_ASYNC16(dst, src) \
    asm volatile("cp.async.cg.shared.global [%0], [%1], 16;" :: "r"(dst), "l"(src))
#define CP_COMMIT() asm volatile("cp.async.commit_group;" ::: "memory")
#define CP_WAIT0()  asm volatile("cp.async.wait_group 0;" ::: "memory")

#define LDSM4(r0, r1, r2, r3, a) \
    asm volatile("ldmatrix.sync.aligned.m8n8.x4.shared.b16 {%0,%1,%2,%3}, [%4];" \
        : "=r"(r0), "=r"(r1), "=r"(r2), "=r"(r3) : "r"(a))

#define MMA_BF16(c, A, b0, b1) \
    asm volatile("mma.sync.aligned.m16n8k16.row.col.f32.bf16.bf16.f32 " \
        "{%0,%1,%2,%3},{%4,%5,%6,%7},{%8,%9},{%0,%1,%2,%3};" \
        : "+f"((c)[0]), "+f"((c)[1]), "+f"((c)[2]), "+f"((c)[3]) \
        : "r"((A)[0]), "r"((A)[1]), "r"((A)[2]), "r"((A)[3]), "r"(b0), "r"(b1))

// ---------------------------------------------------------------------------
// Kernel 1 (fused prep): block b computes inp[b,:] AND splits its 1/32 slice
// of W_ctx into bf16 hi/lo.
// ---------------------------------------------------------------------------
__global__ __launch_bounds__(256) void k_prep(const float* __restrict__ x,
                                              const float* __restrict__ W_in,
                                              const float* __restrict__ b_in,
                                              const float* __restrict__ W_ctx) {
    int b = blockIdx.x, h = threadIdx.x;
    __shared__ float xs[HH];
    xs[h] = x[b * HH + h];
    __syncthreads();
    float acc = b_in[h];
    const float* w = W_in + h * HH;
#pragma unroll 8
    for (int d0 = 0; d0 < HH; d0 += 4) {
        float4 w4 = *(const float4*)(w + d0);
        acc += xs[d0] * w4.x + xs[d0+1] * w4.y + xs[d0+2] * w4.z + xs[d0+3] * w4.w;
    }
    g_inp[b * HH + h] = acc;

#pragma unroll
    for (int r = 0; r < 8; r++) {
        int i = b * 2048 + h + 256 * r;
        float v = W_ctx[i];
        __nv_bfloat16 hi = __float2bfloat16_rn(v);
        g_Bh[i] = hi;
        g_Bl[i] = __float2bfloat16_rn(v - __bfloat162float(hi));
    }
}

// ---------------------------------------------------------------------------
// Kernel 2: split-bf16 HMMA GEMM + fused tanh-dot epilogue.
// CTA: M=128 seq rows, N=256 (all h), K=256 in 8 tiles of 32, double-buffered.
// 512 threads, 16 warps: wm = wid&3 (32 rows), wn = wid>>2 (64 cols).
// acc = Ah*Bh + Ah*Bl + Al*Bh   (lo*lo dropped ~2^-18)
// Pipeline invariant: entering iteration kt, register a4 holds A(stage kt+1);
// it is stored to smem BEFORE being reloaded with stage kt+2.
// ---------------------------------------------------------------------------
#define MT 128
#define KT 32
#define NT (DD / KT)
#define PITCH 80
// smem byte offsets
#define OFF_AH  0          // + s*10240   (128 rows * 80B)
#define OFF_AL  20480      // + s*10240
#define OFF_BH  40960      // + s*20480   (256 rows * 80B)
#define OFF_BL  81920      // + s*20480
#define OFF_IB  122880     // 256 floats
#define OFF_V   123904     // 256 floats
#define OFF_P   124928     // 128 rows x 4 floats
#define SMEM_TOTAL 126976

__global__ __launch_bounds__(512, 1) void k_main(const float* __restrict__ context,
                                                 const float* __restrict__ b_ctx,
                                                 const float* __restrict__ V) {
    extern __shared__ char smem[];
    uint32_t sb = smem_u32(smem);
    int tid = threadIdx.x;
    int wid = tid >> 5, lid = tid & 31;
    int wm = wid & 3, wn = wid >> 2;
    int b = blockIdx.y;
    int m0 = blockIdx.x * MT;

    float* ibs = (float*)(smem + OFF_IB);
    float* vvs = (float*)(smem + OFF_V);
    if (tid < 256) {
        ibs[tid] = g_inp[b * HH + tid] + b_ctx[tid];
        vvs[tid] = V[tid];
    }

    const float* ctx = context + ((long)b * SS + m0) * DD;

#define LDG_A(dst, k0) { \
        _Pragma("unroll") \
        for (int r = 0; r < 2; r++) { \
            int f = tid + 512 * r; \
            dst[r] = *(const float4*)(ctx + (f >> 3) * DD + (k0) + (f & 7) * 4); \
        } \
    }
#define STS_A(src, s) { \
        _Pragma("unroll") \
        for (int r = 0; r < 2; r++) { \
            int f = tid + 512 * r; \
            float4 v4 = src[r]; \
            __nv_bfloat16 h0 = __float2bfloat16_rn(v4.x), h1 = __float2bfloat16_rn(v4.y); \
            __nv_bfloat16 h2 = __float2bfloat16_rn(v4.z), h3 = __float2bfloat16_rn(v4.w); \
            __nv_bfloat16 l0 = __float2bfloat16_rn(v4.x - __bfloat162float(h0)); \
            __nv_bfloat16 l1 = __float2bfloat16_rn(v4.y - __bfloat162float(h1)); \
            __nv_bfloat16 l2 = __float2bfloat16_rn(v4.z - __bfloat162float(h2)); \
            __nv_bfloat16 l3 = __float2bfloat16_rn(v4.w - __bfloat162float(h3)); \
            uint2 ph = make_uint2((uint32_t)__bfloat16_as_ushort(h0) | ((uint32_t)__bfloat16_as_ushort(h1) << 16), \
                                  (uint32_t)__bfloat16_as_ushort(h2) | ((uint32_t)__bfloat16_as_ushort(h3) << 16)); \
            uint2 pl = make_uint2((uint32_t)__bfloat16_as_ushort(l0) | ((uint32_t)__bfloat16_as_ushort(l1) << 16), \
                                  (uint32_t)__bfloat16_as_ushort(l2) | ((uint32_t)__bfloat16_as_ushort(l3) << 16)); \
            char* base = smem + (s) * 10240 + (f >> 3) * PITCH + (f & 7) * 8; \
            *(uint2*)(base + OFF_AH) = ph; \
            *(uint2*)(base + OFF_AL) = pl; \
        } \
    }
#define ISSUE_B(k0, s) { \
        _Pragma("unroll") \
        for (int r = 0; r < 4; r++) { \
            int idx = tid + 512 * r; \
            int mat = idx >> 10, rem = idx & 1023; \
            int row = rem >> 2, cc = rem & 3; \
            const __nv_bfloat16* src = (mat ? g_Bl : g_Bh) + row * DD + (k0) + cc * 8; \
            uint32_t dst = sb + OFF_BH + mat * (OFF_BL - OFF_BH) + (s) * 20480 + row * PITCH + cc * 16; \
            CP_ASYNC16(dst, src); \
        } \
        CP_COMMIT(); \
    }

    // ---- prologue: B(0) in flight; A(0) stored; a4 = A(1) ----
    ISSUE_B(0, 0)
    float4 a4[2];
    LDG_A(a4, 0)
    STS_A(a4, 0)
    LDG_A(a4, KT)

    float c[2][8][4];
#pragma unroll
    for (int mi = 0; mi < 2; mi++)
#pragma unroll
        for (int j = 0; j < 8; j++)
#pragma unroll
            for (int e = 0; e < 4; e++) c[mi][j][e] = 0.f;

#pragma unroll 1
    for (int kt = 0; kt < NT; kt++) {
        int s = kt & 1;
        CP_WAIT0();                      // B stage kt landed
        __syncthreads();                 // stage kt (A+B) visible; s^1 slots free
        if (kt < NT - 1) {
            ISSUE_B((kt + 1) * KT, s ^ 1)
            STS_A(a4, s ^ 1);            // a4 holds A(kt+1) -> store BEFORE reload
            if (kt < NT - 2) LDG_A(a4, (kt + 2) * KT)
        }

        // ---- MMAs over stage kt ----
        uint32_t abase = sb + s * 10240;
        uint32_t bbase = sb + OFF_BH + s * 20480;
#pragma unroll
        for (int ks = 0; ks < 2; ks++) {
            uint32_t aH[2][4], aL[2][4], bH[4][4], bL[4][4];
            int arow_f = wm * 32 + (lid & 15);
            int acol_b = ks * 32 + (lid >> 4) * 16;
#pragma unroll
            for (int mi = 0; mi < 2; mi++) {
                uint32_t ad = abase + (arow_f + mi * 16) * PITCH + acol_b;
                LDSM4(aH[mi][0], aH[mi][1], aH[mi][2], aH[mi][3], ad + OFF_AH);
                LDSM4(aL[mi][0], aL[mi][1], aL[mi][2], aL[mi][3], ad + OFF_AL);
            }
            int brow_f = wn * 64 + (lid & 7) + ((lid >> 4) * 8);
            int bcol_b = ks * 32 + ((lid >> 3) & 1) * 16;
#pragma unroll
            for (int jp = 0; jp < 4; jp++) {
                uint32_t bd = bbase + (brow_f + jp * 16) * PITCH + bcol_b;
                LDSM4(bH[jp][0], bH[jp][1], bH[jp][2], bH[jp][3], bd);
                LDSM4(bL[jp][0], bL[jp][1], bL[jp][2], bL[jp][3], bd + (OFF_BL - OFF_BH));
            }
#pragma unroll
            for (int mi = 0; mi < 2; mi++)
#pragma unroll
                for (int j = 0; j < 8; j++) {
                    uint32_t h0 = bH[j >> 1][(j & 1) * 2], h1 = bH[j >> 1][(j & 1) * 2 + 1];
                    uint32_t l0 = bL[j >> 1][(j & 1) * 2], l1 = bL[j >> 1][(j & 1) * 2 + 1];
                    MMA_BF16(c[mi][j], aH[mi], h0, h1);
                    MMA_BF16(c[mi][j], aH[mi], l0, l1);
                    MMA_BF16(c[mi][j], aL[mi], h0, h1);
                }
        }
    }

    // ---- epilogue: per-row tanh-dot with V ----
    {
        int q = lid & 3, g = lid >> 2;
        float ps[2][2] = {{0.f, 0.f}, {0.f, 0.f}};
#pragma unroll
        for (int mi = 0; mi < 2; mi++)
#pragma unroll
            for (int j = 0; j < 8; j++) {
                int h0 = wn * 64 + j * 8 + q * 2;
                ps[mi][0] += vvs[h0]   * tanhf(c[mi][j][0] + ibs[h0]);
                ps[mi][0] += vvs[h0+1] * tanhf(c[mi][j][1] + ibs[h0+1]);
                ps[mi][1] += vvs[h0]   * tanhf(c[mi][j][2] + ibs[h0]);
                ps[mi][1] += vvs[h0+1] * tanhf(c[mi][j][3] + ibs[h0+1]);
            }
#pragma unroll
        for (int off = 1; off <= 2; off <<= 1) {
#pragma unroll
            for (int mi = 0; mi < 2; mi++) {
                ps[mi][0] += __shfl_xor_sync(0xffffffffu, ps[mi][0], off);
                ps[mi][1] += __shfl_xor_sync(0xffffffffu, ps[mi][1], off);
            }
        }
        float* part = (float*)(smem + OFF_P);
        __syncthreads();
        if (q == 0) {
#pragma unroll
            for (int mi = 0; mi < 2; mi++) {
                part[(wm * 32 + mi * 16 + g) * 4 + wn]     = ps[mi][0];
                part[(wm * 32 + mi * 16 + g + 8) * 4 + wn] = ps[mi][1];
            }
        }
        __syncthreads();
        if (tid < MT) {
            float ssum = part[tid * 4] + part[tid * 4 + 1] + part[tid * 4 + 2] + part[tid * 4 + 3];
            g_att[b * SS + m0 + tid] = 10.f * tanhf(ssum);
        }
    }
}

// ---------------------------------------------------------------------------
// Kernel 3: mask echo + single-pass masked argmax + p = exp(max)/sum(exp).
// ---------------------------------------------------------------------------
__global__ __launch_bounds__(1024) void k_reduce(const int* __restrict__ mask,
                                                 float* __restrict__ out) {
    int b = blockIdx.x, tid = threadIdx.x;
    __shared__ float smax[1024], ssum[1024];
    __shared__ int   sidx[1024];

    float best = -INFINITY, se = 0.f;
    int bidx = 0x7fffffff;
    for (int s = tid; s < SS; s += 1024) {
        int m = mask[b * SS + s];
        out[2 * BB + b * SS + s] = m ? 1.f : 0.f;
        if (m) {
            float v = g_att[b * SS + s];
            se += expf(v);
            if (v > best || (v == best && s < bidx)) { best = v; bidx = s; }
        }
    }
    smax[tid] = best; sidx[tid] = bidx; ssum[tid] = se;
    __syncthreads();
    for (int off = 512; off; off >>= 1) {
        if (tid < off) {
            float v = smax[tid + off]; int ix = sidx[tid + off];
            if (v > smax[tid] || (v == smax[tid] && ix < sidx[tid])) {
                smax[tid] = v; sidx[tid] = ix;
            }
            ssum[tid] += ssum[tid + off];
        }
        __syncthreads();
    }
    if (tid == 0) {
        float rowmax = smax[0];
        out[b]      = (float)((rowmax == -INFINITY) ? 0 : sidx[0]);
        out[BB + b] = expf(rowmax) / ssum[0];
    }
}

// ---------------------------------------------------------------------------
extern "C" void kernel_launch(void* const* d_in, const int* in_sizes, int n_in,
                              void* d_out, int out_size) {
    const float* x      = (const float*)d_in[0];
    const float* contex = (const float*)d_in[1];
    const int*   mask   = (const int*)  d_in[2];
    const float* W_in   = (const float*)d_in[3];
    const float* b_in   = (const float*)d_in[4];
    const float* W_ctx  = (const float*)d_in[5];
    const float* b_ctx  = (const float*)d_in[6];
    const float* V      = (const float*)d_in[7];
    float* out = (float*)d_out;

    cudaFuncSetAttribute(k_main, cudaFuncAttributeMaxDynamicSharedMemorySize, SMEM_TOTAL);

    k_prep<<<BB, 256>>>(x, W_in, b_in, W_ctx);
    k_main<<<dim3(SS / MT, BB), 512, SMEM_TOTAL>>>(contex, b_ctx, V);
    k_reduce<<<BB, 1024>>>(mask, out);
}

// round 11
// speedup vs baseline: 1.0830x; 1.0218x over previous
#include <cuda_runtime.h>
#include <cuda_bf16.h>
#include <math.h>
#include <stdint.h>

#define BB 32
#define SS 8192
#define DD 256
#define HH 256

// device-global scratch (allocation-free rule)
__device__ float g_inp[BB * HH];
__device__ __nv_bfloat16 g_Bh[HH * DD];      // W_ctx hi (bf16), [h][d]
__device__ __nv_bfloat16 g_Bl[HH * DD];      // W_ctx lo
__device__ float g_att[BB * SS];             // raw tanh-dot sums (pre 10*tanh)

// ---------------------------------------------------------------------------
__device__ __forceinline__ uint32_t smem_u32(const void* p) {
    uint32_t a;
    asm("{ .reg .u64 t; cvta.to.shared.u64 t, %1; cvt.u32.u64 %0, t; }" : "=r"(a) : "l"(p));
    return a;
}
#define CP_ASYNC16(dst, src) \
    asm volatile("cp.async.cg.shared.global [%0], [%1], 16;" :: "r"(dst), "l"(src))
#define CP_COMMIT() asm volatile("cp.async.commit_group;" ::: "memory")
#define CP_WAIT0()  asm volatile("cp.async.wait_group 0;" ::: "memory")

#define LDSM4(r0, r1, r2, r3, a) \
    asm volatile("ldmatrix.sync.aligned.m8n8.x4.shared.b16 {%0,%1,%2,%3}, [%4];" \
        : "=r"(r0), "=r"(r1), "=r"(r2), "=r"(r3) : "r"(a))

#define MMA_BF16(c, A, b0, b1) \
    asm volatile("mma.sync.aligned.m16n8k16.row.col.f32.bf16.bf16.f32 " \
        "{%0,%1,%2,%3},{%4,%5,%6,%7},{%8,%9},{%0,%1,%2,%3};" \
        : "+f"((c)[0]), "+f"((c)[1]), "+f"((c)[2]), "+f"((c)[3]) \
        : "r"((A)[0]), "r"((A)[1]), "r"((A)[2]), "r"((A)[3]), "r"(b0), "r"(b1))

// ---------------------------------------------------------------------------
// Kernel 1: inp[b,h] = b_in[h] + sum_d x[b,d] * W_in[h,d]
// ---------------------------------------------------------------------------
__global__ void k_inp(const float* __restrict__ x, const float* __restrict__ W_in,
                      const float* __restrict__ b_in) {
    int b = blockIdx.x, h = threadIdx.x;
    __shared__ float xs[HH];
    xs[h] = x[b * HH + h];
    __syncthreads();
    float acc = b_in[h];
    const float* w = W_in + h * HH;
#pragma unroll 8
    for (int d0 = 0; d0 < HH; d0 += 4) {
        float4 w4 = *(const float4*)(w + d0);
        acc += xs[d0] * w4.x + xs[d0+1] * w4.y + xs[d0+2] * w4.z + xs[d0+3] * w4.w;
    }
    g_inp[b * HH + h] = acc;
}

// ---------------------------------------------------------------------------
// Kernel 2: split W_ctx fp32 -> bf16 hi/lo
// ---------------------------------------------------------------------------
__global__ void k_wsplit(const float* __restrict__ W) {
    int i = blockIdx.x * 256 + threadIdx.x;
    float v = W[i];
    __nv_bfloat16 h = __float2bfloat16_rn(v);
    g_Bh[i] = h;
    g_Bl[i] = __float2bfloat16_rn(v - __bfloat162float(h));
}

// ---------------------------------------------------------------------------
// Kernel 3: zero g_att (graph replays need fresh zeros for atomic combine)
// ---------------------------------------------------------------------------
__global__ void k_zero() {
    int i = blockIdx.x * blockDim.x + threadIdx.x;
    ((float4*)g_att)[i] = make_float4(0.f, 0.f, 0.f, 0.f);
}

// ---------------------------------------------------------------------------
// Kernel 4: split-bf16 HMMA GEMM, N split across 2 CTAs (blockIdx.z).
// CTA: M=64 rows, N=128 cols (its n-half), K=256 in 8 tiles of 32, 2-stage.
// 8 warps: wm = wid&1 (32 rows), wn = wid>>1 (32 cols each).
// acc = Ah*Bh + Ah*Bl + Al*Bh  (lo*lo dropped ~2^-18)
// Epilogue: per-row partial tanh-dot over this CTA's 128 h, combined across
// the two n-half CTAs via atomicAdd into zeroed g_att (2 commutative adds
// per row -> bitwise deterministic). k_reduce applies the final 10*tanh.
// 3 CTAs/SM (6 warps/SMSP) — the point of this round.
// ---------------------------------------------------------------------------
#define MT 64
#define KT 32
#define NT (DD / KT)
#define PITCH 80
// smem byte offsets
#define OFF_A   0          // + s*10240; hi at +0, lo at +5120 (64 rows * 80B)
#define OFF_BH  20480      // + s*10240  (128 rows * 80B)
#define OFF_BL  40960      // + s*10240
#define OFF_IB  61440      // 256 floats
#define OFF_V   62464      // 256 floats
#define OFF_P   63488      // 64 rows x 4 floats
#define SMEM_TOTAL 64512

__global__ __launch_bounds__(256, 3) void k_main(const float* __restrict__ context,
                                                 const float* __restrict__ b_ctx,
                                                 const float* __restrict__ V) {
    extern __shared__ char smem[];
    uint32_t sb = smem_u32(smem);
    int tid = threadIdx.x;
    int wid = tid >> 5, lid = tid & 31;
    int wm = wid & 1, wn = wid >> 1;
    int b = blockIdx.y;
    int m0 = blockIdx.x * MT;
    int hb = blockIdx.z * 128;            // this CTA's n-half base

    float* ibs = (float*)(smem + OFF_IB);
    float* vvs = (float*)(smem + OFF_V);
    ibs[tid] = g_inp[b * HH + tid] + b_ctx[tid];
    vvs[tid] = V[tid];

    const float* ctx = context + ((long)b * SS + m0) * DD;
    int arow = tid >> 2, aseg = tid & 3;

#define ISSUE_B(k0, s) { \
        _Pragma("unroll") \
        for (int r = 0; r < 4; r++) { \
            int idx = tid + 256 * r; \
            int mat = idx >> 9, rem = idx & 511; \
            int row = rem >> 2, cc = rem & 3; \
            const __nv_bfloat16* src = (mat ? g_Bl : g_Bh) + (hb + row) * DD + (k0) + cc * 8; \
            uint32_t dst = sb + OFF_BH + mat * 20480 + (s) * 10240 + row * PITCH + cc * 16; \
            CP_ASYNC16(dst, src); \
        } \
        CP_COMMIT(); \
    }
#define STS_A(s) { \
        float f[8] = {a0.x, a0.y, a0.z, a0.w, a1.x, a1.y, a1.z, a1.w}; \
        uint32_t hi[4], lo[4]; \
        _Pragma("unroll") \
        for (int e = 0; e < 4; e++) { \
            __nv_bfloat16 h0 = __float2bfloat16_rn(f[2*e]); \
            __nv_bfloat16 h1 = __float2bfloat16_rn(f[2*e+1]); \
            __nv_bfloat16 l0 = __float2bfloat16_rn(f[2*e]   - __bfloat162float(h0)); \
            __nv_bfloat16 l1 = __float2bfloat16_rn(f[2*e+1] - __bfloat162float(h1)); \
            hi[e] = (uint32_t)__bfloat16_as_ushort(h0) | ((uint32_t)__bfloat16_as_ushort(h1) << 16); \
            lo[e] = (uint32_t)__bfloat16_as_ushort(l0) | ((uint32_t)__bfloat16_as_ushort(l1) << 16); \
        } \
        char* base = smem + OFF_A + (s) * 10240 + arow * PITCH + aseg * 16; \
        *(uint4*)(base)        = make_uint4(hi[0], hi[1], hi[2], hi[3]); \
        *(uint4*)(base + 5120) = make_uint4(lo[0], lo[1], lo[2], lo[3]); \
    }

    // ---- prologue: B(0) in flight; A(0) in regs
    ISSUE_B(0, 0)
    float4 a0 = *(const float4*)(ctx + arow * DD + aseg * 8);
    float4 a1 = *(const float4*)(ctx + arow * DD + aseg * 8 + 4);

    float c[2][4][4];
#pragma unroll
    for (int mi = 0; mi < 2; mi++)
#pragma unroll
        for (int j = 0; j < 4; j++)
#pragma unroll
            for (int e = 0; e < 4; e++) c[mi][j][e] = 0.f;

#pragma unroll 1
    for (int kt = 0; kt < NT; kt++) {
        int s = kt & 1;
        STS_A(s);                         // A(kt) regs -> smem stage s
        CP_WAIT0();                       // B(kt) landed
        __syncthreads();                  // stage s visible; prev readers done
        if (kt < NT - 1) {
            int k0 = (kt + 1) * KT;
            ISSUE_B(k0, s ^ 1)
            a0 = *(const float4*)(ctx + arow * DD + k0 + aseg * 8);
            a1 = *(const float4*)(ctx + arow * DD + k0 + aseg * 8 + 4);
        }

        // ---- MMAs over stage kt
        uint32_t abase = sb + OFF_A + s * 10240;
        uint32_t bbase = sb + OFF_BH + s * 10240;
#pragma unroll
        for (int ks = 0; ks < 2; ks++) {
            uint32_t aH[2][4], aL[2][4], bH[2][4], bL[2][4];
            int arow_f = wm * 32 + (lid & 15);
            int acol_b = ks * 32 + (lid >> 4) * 16;
#pragma unroll
            for (int mi = 0; mi < 2; mi++) {
                uint32_t ad = abase + (arow_f + mi * 16) * PITCH + acol_b;
                LDSM4(aH[mi][0], aH[mi][1], aH[mi][2], aH[mi][3], ad);
                LDSM4(aL[mi][0], aL[mi][1], aL[mi][2], aL[mi][3], ad + 5120);
            }
            int brow_f = wn * 32 + (lid & 7) + ((lid >> 4) * 8);
            int bcol_b = ks * 32 + ((lid >> 3) & 1) * 16;
#pragma unroll
            for (int jp = 0; jp < 2; jp++) {
                uint32_t bd = bbase + (brow_f + jp * 16) * PITCH + bcol_b;
                LDSM4(bH[jp][0], bH[jp][1], bH[jp][2], bH[jp][3], bd);
                LDSM4(bL[jp][0], bL[jp][1], bL[jp][2], bL[jp][3], bd + 20480);
            }
#pragma unroll
            for (int mi = 0; mi < 2; mi++)
#pragma unroll
                for (int j = 0; j < 4; j++) {
                    uint32_t h0 = bH[j >> 1][(j & 1) * 2], h1 = bH[j >> 1][(j & 1) * 2 + 1];
                    uint32_t l0 = bL[j >> 1][(j & 1) * 2], l1 = bL[j >> 1][(j & 1) * 2 + 1];
                    MMA_BF16(c[mi][j], aH[mi], h0, h1);
                    MMA_BF16(c[mi][j], aH[mi], l0, l1);
                    MMA_BF16(c[mi][j], aL[mi], h0, h1);
                }
        }
    }

    // ---- epilogue: partial tanh-dot over this CTA's 128 h
    {
        int q = lid & 3, g = lid >> 2;
        float ps[2][2] = {{0.f, 0.f}, {0.f, 0.f}};
#pragma unroll
        for (int mi = 0; mi < 2; mi++)
#pragma unroll
            for (int j = 0; j < 4; j++) {
                int h0 = hb + wn * 32 + j * 8 + q * 2;
                ps[mi][0] += vvs[h0]   * tanhf(c[mi][j][0] + ibs[h0]);
                ps[mi][0] += vvs[h0+1] * tanhf(c[mi][j][1] + ibs[h0+1]);
                ps[mi][1] += vvs[h0]   * tanhf(c[mi][j][2] + ibs[h0]);
                ps[mi][1] += vvs[h0+1] * tanhf(c[mi][j][3] + ibs[h0+1]);
            }
#pragma unroll
        for (int off = 1; off <= 2; off <<= 1) {
#pragma unroll
            for (int mi = 0; mi < 2; mi++) {
                ps[mi][0] += __shfl_xor_sync(0xffffffffu, ps[mi][0], off);
                ps[mi][1] += __shfl_xor_sync(0xffffffffu, ps[mi][1], off);
            }
        }
        float* part = (float*)(smem + OFF_P);
        __syncthreads();
        if (q == 0) {
#pragma unroll
            for (int mi = 0; mi < 2; mi++) {
                part[(wm * 32 + mi * 16 + g) * 4 + wn]     = ps[mi][0];
                part[(wm * 32 + mi * 16 + g + 8) * 4 + wn] = ps[mi][1];
            }
        }
        __syncthreads();
        if (tid < MT) {
            float ssum = part[tid * 4] + part[tid * 4 + 1] + part[tid * 4 + 2] + part[tid * 4 + 3];
            atomicAdd(&g_att[b * SS + m0 + tid], ssum);   // 2 adds/row, commutative
        }
    }
}

// ---------------------------------------------------------------------------
// Kernel 5: mask echo + masked argmax + p = exp(max)/sum(exp).
// g_att holds raw sums; apply att = 10*tanh(v) here. att in [-10,10].
// ---------------------------------------------------------------------------
__global__ __launch_bounds__(1024) void k_reduce(const int* __restrict__ mask,
                                                 float* __restrict__ out) {
    int b = blockIdx.x, tid = threadIdx.x;
    __shared__ float smax[1024], ssum[1024];
    __shared__ int   sidx[1024];

    float best = -INFINITY, se = 0.f;
    int bidx = 0x7fffffff;
    for (int s = tid; s < SS; s += 1024) {
        int m = mask[b * SS + s];
        out[2 * BB + b * SS + s] = m ? 1.f : 0.f;
        if (m) {
            float v = 10.f * tanhf(g_att[b * SS + s]);
            se += expf(v);
            if (v > best || (v == best && s < bidx)) { best = v; bidx = s; }
        }
    }
    smax[tid] = best; sidx[tid] = bidx; ssum[tid] = se;
    __syncthreads();
    for (int off = 512; off; off >>= 1) {
        if (tid < off) {
            float v = smax[tid + off]; int ix = sidx[tid + off];
            if (v > smax[tid] || (v == smax[tid] && ix < sidx[tid])) {
                smax[tid] = v; sidx[tid] = ix;
            }
            ssum[tid] += ssum[tid + off];
        }
        __syncthreads();
    }
    if (tid == 0) {
        float rowmax = smax[0];
        out[b]      = (float)((rowmax == -INFINITY) ? 0 : sidx[0]);
        out[BB + b] = expf(rowmax) / ssum[0];
    }
}

// ---------------------------------------------------------------------------
extern "C" void kernel_launch(void* const* d_in, const int* in_sizes, int n_in,
                              void* d_out, int out_size) {
    const float* x      = (const float*)d_in[0];
    const float* contex = (const float*)d_in[1];
    const int*   mask   = (const int*)  d_in[2];
    const float* W_in   = (const float*)d_in[3];
    const float* b_in   = (const float*)d_in[4];
    const float* W_ctx  = (const float*)d_in[5];
    const float* b_ctx  = (const float*)d_in[6];
    const float* V      = (const float*)d_in[7];
    float* out = (float*)d_out;

    cudaFuncSetAttribute(k_main, cudaFuncAttributeMaxDynamicSharedMemorySize, SMEM_TOTAL);

    k_inp<<<BB, HH>>>(x, W_in, b_in);
    k_wsplit<<<HH * DD / 256, 256>>>(W_ctx);
    k_zero<<<BB * SS / 4 / 256, 256>>>();
    k_main<<<dim3(SS / MT, BB, 2), 256, SMEM_TOTAL>>>(contex, b_ctx, V);
    k_reduce<<<BB, 1024>>>(mask, out);
}